// round 5
// baseline (speedup 1.0000x reference)
#include <cuda_runtime.h>
#include <cstdint>

// ---------------- problem dims ----------------
#define K_HALF 24
#define S_DIM  64
#define D_DIM  256
#define L_DIM  1024
#define B_SZ   4
#define KX     8
#define O_DIM  48                      // 2*K_HALF
#define K_G    16384                   // D_DIM * S_DIM  (k = d*64 + s)
#define K_TOT  18432                   // K_G + KX*D_DIM (k = 16384 + j*256 + d)
#define M_ROWS 4096                    // B_SZ * L_DIM
#define E_DIM  256
#define KSPLIT 4

// ---------------- scratch (device globals; no cudaMalloc allowed) ----------------
__device__ float g_Aext[(size_t)M_ROWS * K_TOT];               // 302 MB: [m][k]
__device__ float g_Pt[(size_t)E_DIM * K_TOT];                  //  19 MB: [e][k]
__device__ float g_part[KSPLIT][(size_t)M_ROWS * E_DIM];       //  16 MB: split-K partials

// ---------------- helpers ----------------
__device__ __forceinline__ uint32_t smem_u32(const void* p) {
    uint32_t a;
    asm("{ .reg .u64 t; cvta.to.shared.u64 t, %1; cvt.u32.u64 %0, t; }" : "=r"(a) : "l"(p));
    return a;
}

__device__ __forceinline__ float to_tf32(float v) {
    uint32_t u;
    asm("cvt.rna.tf32.f32 %0, %1;" : "=r"(u) : "f"(v));
    return __uint_as_float(u);
}

__device__ __forceinline__ void cp_async16(uint32_t dst, const void* src) {
    asm volatile("cp.async.cg.shared.global [%0], [%1], 16;" :: "r"(dst), "l"(src));
}
__device__ __forceinline__ void cp_commit() {
    asm volatile("cp.async.commit_group;" ::: "memory");
}

// m16n8k8 tf32 mma, D += A*B (fp32 accum in place)
__device__ __forceinline__ void mma8(float* d, const uint32_t* a, const uint32_t* b) {
    asm volatile(
        "mma.sync.aligned.m16n8k8.row.col.f32.tf32.tf32.f32 "
        "{%0,%1,%2,%3},{%4,%5,%6,%7},{%8,%9},{%0,%1,%2,%3};"
        : "+f"(d[0]), "+f"(d[1]), "+f"(d[2]), "+f"(d[3])
        : "r"(a[0]), "r"(a[1]), "r"(a[2]), "r"(a[3]), "r"(b[0]), "r"(b[1]));
}

__device__ __forceinline__ void ldsm4(uint32_t* r, uint32_t addr) {
    asm volatile("ldmatrix.sync.aligned.m8n8.x4.shared.b16 {%0,%1,%2,%3}, [%4];"
        : "=r"(r[0]), "=r"(r[1]), "=r"(r[2]), "=r"(r[3]) : "r"(addr));
}

// ---------------- kernel: precompute Pt[e][k] (tf32-rounded) ----------------
__global__ void k_prep(const float* __restrict__ C, const float* __restrict__ Bv,
                       const float* __restrict__ M, const float* __restrict__ Mp,
                       const float* __restrict__ Mm) {
    int d  = blockIdx.x;          // 0..255
    int s  = threadIdx.x & 63;    // warp lanes span s => coalesced Pt writes
    int eg = threadIdx.x >> 6;    // 0..3

    float cs[O_DIM];
#pragma unroll
    for (int o = 0; o < O_DIM; o++) cs[o] = C[s * O_DIM + o];
    float bv = Bv[s];

    for (int e = eg * 64; e < eg * 64 + 64; e++) {
        float acc = 0.0f;
#pragma unroll
        for (int o = 0; o < O_DIM; o++) {
            float w = (o < K_HALF) ? __ldg(&Mp[((size_t)o * D_DIM + d) * D_DIM + e])
                                   : __ldg(&Mm[((size_t)(o - K_HALF) * D_DIM + d) * D_DIM + e]);
            acc = fmaf(cs[o], w, acc);
        }
        g_Pt[(size_t)e * K_TOT + d * S_DIM + s] = to_tf32(bv * acc);
    }

    if (s < KX) {
        int j = s;
        float mj[O_DIM];
#pragma unroll
        for (int o = 0; o < O_DIM; o++) mj[o] = M[o * KX + j];   // M is (48, 8, 1)
        for (int e = eg * 64; e < eg * 64 + 64; e++) {
            float acc = 0.0f;
#pragma unroll
            for (int o = 0; o < O_DIM; o++) {
                float w = (o < K_HALF) ? __ldg(&Mp[((size_t)o * D_DIM + d) * D_DIM + e])
                                       : __ldg(&Mm[((size_t)(o - K_HALF) * D_DIM + d) * D_DIM + e]);
                acc = fmaf(mj[o], w, acc);
            }
            g_Pt[(size_t)e * K_TOT + K_G + j * D_DIM + d] = to_tf32(acc);
        }
    }
}

// ---------------- kernel: LDS scan -> g_Aext[m][d*64+s]  (half: 512 bd each) ----
__global__ void k_scan(const float* __restrict__ x, const float* __restrict__ A, int off) {
    int s    = threadIdx.x & 63;
    int half = threadIdx.x >> 6;
    int bd   = (blockIdx.x + off) * 2 + half;   // 0..1023
    int b    = bd >> 8;
    int d    = bd & 255;

    float a = A[s];
    float h = 0.0f;
    const float* xp = x + (size_t)b * L_DIM * D_DIM + d;
    float* op = g_Aext + (size_t)b * L_DIM * K_TOT + d * S_DIM + s;

#pragma unroll 1
    for (int l = 0; l < L_DIM; l += 4) {
        float x0 = __ldg(xp + (size_t)l * D_DIM);
        float x1 = __ldg(xp + (size_t)(l + 1) * D_DIM);
        float x2 = __ldg(xp + (size_t)(l + 2) * D_DIM);
        float x3 = __ldg(xp + (size_t)(l + 3) * D_DIM);
        h = fmaf(h, a, x0); op[(size_t)l * K_TOT]       = to_tf32(h);
        h = fmaf(h, a, x1); op[(size_t)(l + 1) * K_TOT] = to_tf32(h);
        h = fmaf(h, a, x2); op[(size_t)(l + 2) * K_TOT] = to_tf32(h);
        h = fmaf(h, a, x3); op[(size_t)(l + 3) * K_TOT] = to_tf32(h);
    }
}

// ---------------- kernel: shift taps (float4), half: j in [jh*4, jh*4+4) ------
__global__ void k_shift(const float* __restrict__ x, int jh) {
    int idx = blockIdx.x * 256 + threadIdx.x;   // 4096 * 4 * 64 = 1,048,576 per half
    int m  = idx >> 8;
    int r  = idx & 255;
    int j  = jh * 4 + (r >> 6);
    int d4 = r & 63;
    int b  = m >> 10;
    int l  = m & 1023;
    float4 v = make_float4(0.f, 0.f, 0.f, 0.f);
    if (l >= j)
        v = *(const float4*)(x + ((size_t)b * L_DIM + (l - j)) * D_DIM + d4 * 4);
    v.x = to_tf32(v.x); v.y = to_tf32(v.y); v.z = to_tf32(v.z); v.w = to_tf32(v.w);
    *(float4*)(g_Aext + (size_t)m * K_TOT + K_G + j * D_DIM + d4 * 4) = v;
}

// ---------------- GEMM  part[y][m][e] = sum_k A[m][k] * Pt[e][k] ----------------
// CTA tile 128(M) x 256(N); 8 warps as 2(M) x 4(N); warp tile 64x64.
// 4-stage cp.async pipeline (prefetch depth 3), KTILE=32, double-buffered
// register fragments via ldmatrix.x4. Epilogue: plain float2 stores to g_part.
#define NST   4
#define KTILE 32
#define KCH   (K_TOT / KSPLIT)          // 4608
#define NSTG  (KCH / KTILE)             // 144
#define A_STG 16384                     // 128 rows * 128B
#define B_STG 32768                     // 256 rows * 128B
#define STG   (A_STG + B_STG)           // 49152
#define SMEM_DYN (NST * STG)            // 196608

__global__ void __launch_bounds__(256, 1)
k_gemm() {
    extern __shared__ char smem[];
    uint32_t sb = smem_u32(smem);

    int tid  = threadIdx.x;
    int lane = tid & 31;
    int wid  = tid >> 5;
    int wm   = wid >> 2;                 // 0..1
    int wn   = wid & 3;                  // 0..3
    int m0   = blockIdx.x * 128;
    int k0   = blockIdx.y * KCH;

    const float* Ab = g_Aext + (size_t)m0 * K_TOT + k0;
    const float* Bb = g_Pt + k0;

    auto copy_stage = [&](int st) {
        uint32_t base = sb + (st & (NST - 1)) * STG;
        int kf = st * KTILE;
#pragma unroll
        for (int it = 0; it < 12; it++) {
            int id = tid + it * 256;                 // 0..3071 16B chunks
            if (id < 1024) {                         // A: 128 rows x 8 chunks
                int r = id >> 3, ch = id & 7;
                cp_async16(base + r * 128 + ((ch ^ (r & 7)) << 4),
                           Ab + (size_t)r * K_TOT + kf + ch * 4);
            } else {                                 // B: 256 rows x 8 chunks
                int id2 = id - 1024;
                int r = id2 >> 3, ch = id2 & 7;
                cp_async16(base + A_STG + r * 128 + ((ch ^ (r & 7)) << 4),
                           Bb + (size_t)r * K_TOT + kf + ch * 4);
            }
        }
    };

    float acc[4][8][4];
#pragma unroll
    for (int i = 0; i < 4; i++)
#pragma unroll
        for (int j = 0; j < 8; j++)
#pragma unroll
            for (int c = 0; c < 4; c++) acc[i][j][c] = 0.0f;

    copy_stage(0); cp_commit();
    copy_stage(1); cp_commit();
    copy_stage(2); cp_commit();

    // ldmatrix per-lane address components (validated in rounds 2/3):
    int sw   = lane & 7;
    int aRow = (lane & 7) + (((lane >> 3) & 1) << 3);
    int aCb  = lane >> 4;
    int bRow = (lane & 7) + ((lane >> 4) << 3);
    int bCb  = (lane >> 3) & 1;

    int lr = lane >> 2;
    int lc = lane & 3;

    uint32_t aF[2][16], bF[2][16];

    for (int ks = 0; ks < NSTG; ks++) {
        asm volatile("cp.async.wait_group 2;" ::: "memory");
        __syncthreads();
        if (ks + 3 < NSTG) copy_stage(ks + 3);       // buffer (ks-1)%4, freed by the barrier
        cp_commit();

        uint32_t aBase = sb + (ks & (NST - 1)) * STG;
        uint32_t bBase = aBase + A_STG;
        uint32_t aLane = aBase + (wm * 64 + aRow) * 128;
        uint32_t bLane = bBase + (wn * 64 + bRow) * 128;

        // load kk=0 fragments
#pragma unroll
        for (int nfp = 0; nfp < 4; nfp++)
            ldsm4(&bF[0][nfp * 4], bLane + nfp * 16 * 128 + ((bCb ^ sw) << 4));
#pragma unroll
        for (int mf = 0; mf < 4; mf++)
            ldsm4(&aF[0][mf * 4], aLane + mf * 16 * 128 + ((aCb ^ sw) << 4));

#pragma unroll
        for (int kk = 0; kk < 4; kk++) {             // 4 x k8 steps
            int cur = kk & 1;
            if (kk < 3) {                            // prefetch kk+1 fragments
                int nxt = cur ^ 1;
#pragma unroll
                for (int nfp = 0; nfp < 4; nfp++)
                    ldsm4(&bF[nxt][nfp * 4],
                          bLane + nfp * 16 * 128 + (((2 * (kk + 1) + bCb) ^ sw) << 4));
#pragma unroll
                for (int mf = 0; mf < 4; mf++)
                    ldsm4(&aF[nxt][mf * 4],
                          aLane + mf * 16 * 128 + (((2 * (kk + 1) + aCb) ^ sw) << 4));
            }
#pragma unroll
            for (int mf = 0; mf < 4; mf++)
#pragma unroll
                for (int nf = 0; nf < 8; nf++)
                    mma8(acc[mf][nf], &aF[cur][mf * 4],
                         &bF[cur][(nf >> 1) * 4 + (nf & 1) * 2]);
        }
    }

    // epilogue: plain stores to this split's partial buffer
    float* po = g_part[blockIdx.y];
#pragma unroll
    for (int mf = 0; mf < 4; mf++) {
#pragma unroll
        for (int nf = 0; nf < 8; nf++) {
            int r = m0 + wm * 64 + mf * 16 + lr;
            int c = wn * 64 + nf * 8 + (lc << 1);
            *(float2*)&po[(size_t)r * E_DIM + c] =
                make_float2(acc[mf][nf][0], acc[mf][nf][1]);
            *(float2*)&po[(size_t)(r + 8) * E_DIM + c] =
                make_float2(acc[mf][nf][2], acc[mf][nf][3]);
        }
    }
}

// ---------------- reduce: out = sum of KSPLIT partials ----------------
__global__ void k_reduce(float* __restrict__ out, int n4) {
    int i = blockIdx.x * 256 + threadIdx.x;
    if (i >= n4) return;
    float4 a = ((const float4*)g_part[0])[i];
    float4 b = ((const float4*)g_part[1])[i];
    float4 c = ((const float4*)g_part[2])[i];
    float4 d = ((const float4*)g_part[3])[i];
    float4 r;
    r.x = (a.x + b.x) + (c.x + d.x);
    r.y = (a.y + b.y) + (c.y + d.y);
    r.z = (a.z + b.z) + (c.z + d.z);
    r.w = (a.w + b.w) + (c.w + d.w);
    ((float4*)out)[i] = r;
}

// ---------------- launch ----------------
extern "C" void kernel_launch(void* const* d_in, const int* in_sizes, int n_in,
                              void* d_out, int out_size) {
    const float* x  = (const float*)d_in[0];
    const float* A  = (const float*)d_in[1];
    const float* Bv = (const float*)d_in[2];
    const float* C  = (const float*)d_in[3];
    const float* M  = (const float*)d_in[4];
    const float* Mp = (const float*)d_in[5];
    const float* Mm = (const float*)d_in[6];
    float* out = (float*)d_out;

    static bool attr_set = false;
    if (!attr_set) {
        cudaFuncSetAttribute(k_gemm, cudaFuncAttributeMaxDynamicSharedMemorySize, SMEM_DYN);
        attr_set = true;
    }

    // 6 launches before reduce => the 6th launch (ncu -s 5 -c 1) is k_gemm.
    k_prep<<<D_DIM, 256>>>(C, Bv, M, Mp, Mm);
    k_scan<<<256, 128>>>(x, A, 0);
    k_scan<<<256, 128>>>(x, A, 256);
    k_shift<<<4096, 256>>>(x, 0);
    k_shift<<<4096, 256>>>(x, 1);

    dim3 grid(M_ROWS / 128, KSPLIT);
    k_gemm<<<grid, 256, SMEM_DYN>>>();

    int n4 = M_ROWS * E_DIM / 4;
    k_reduce<<<(n4 + 255) / 256, 256>>>(out, n4);
}

// round 6
// speedup vs baseline: 1.2407x; 1.2407x over previous
#include <cuda_runtime.h>
#include <cstdint>

// ---------------- problem dims ----------------
#define K_HALF 24
#define S_DIM  64
#define D_DIM  256
#define L_DIM  1024
#define B_SZ   4
#define KX     8
#define O_DIM  48                      // 2*K_HALF
#define K_G    16384                   // D_DIM * S_DIM  (k = d*64 + s)
#define K_TOT  18432                   // K_G + KX*D_DIM (k = 16384 + j*256 + d)
#define M_ROWS 4096                    // B_SZ * L_DIM
#define E_DIM  256
#define KSPLIT 4

// ---------------- scratch (device globals; no cudaMalloc allowed) ----------------
__device__ float g_Aext[(size_t)M_ROWS * K_TOT];               // 302 MB: [m][k]
__device__ float g_Pt[(size_t)E_DIM * K_TOT];                  //  19 MB: [e][k]
__device__ float g_part[KSPLIT][(size_t)M_ROWS * E_DIM];       //  16 MB: split-K partials

// ---------------- helpers ----------------
__device__ __forceinline__ uint32_t smem_u32(const void* p) {
    uint32_t a;
    asm("{ .reg .u64 t; cvta.to.shared.u64 t, %1; cvt.u32.u64 %0, t; }" : "=r"(a) : "l"(p));
    return a;
}

__device__ __forceinline__ float to_tf32(float v) {
    uint32_t u;
    asm("cvt.rna.tf32.f32 %0, %1;" : "=r"(u) : "f"(v));
    return __uint_as_float(u);
}

__device__ __forceinline__ void cp_async16(uint32_t dst, const void* src) {
    asm volatile("cp.async.cg.shared.global [%0], [%1], 16;" :: "r"(dst), "l"(src));
}
__device__ __forceinline__ void cp_commit() {
    asm volatile("cp.async.commit_group;" ::: "memory");
}

// m16n8k8 tf32 mma, D += A*B (fp32 accum in place)
__device__ __forceinline__ void mma8(float* d, const uint32_t* a, const uint32_t* b) {
    asm volatile(
        "mma.sync.aligned.m16n8k8.row.col.f32.tf32.tf32.f32 "
        "{%0,%1,%2,%3},{%4,%5,%6,%7},{%8,%9},{%0,%1,%2,%3};"
        : "+f"(d[0]), "+f"(d[1]), "+f"(d[2]), "+f"(d[3])
        : "r"(a[0]), "r"(a[1]), "r"(a[2]), "r"(a[3]), "r"(b[0]), "r"(b[1]));
}

__device__ __forceinline__ void ldsm4(uint32_t* r, uint32_t addr) {
    asm volatile("ldmatrix.sync.aligned.m8n8.x4.shared.b16 {%0,%1,%2,%3}, [%4];"
        : "=r"(r[0]), "=r"(r[1]), "=r"(r[2]), "=r"(r[3]) : "r"(addr));
}

// ---------------- kernel: precompute Pt[e][k] (tf32-rounded) ----------------
__global__ void k_prep(const float* __restrict__ C, const float* __restrict__ Bv,
                       const float* __restrict__ M, const float* __restrict__ Mp,
                       const float* __restrict__ Mm) {
    int d  = blockIdx.x;          // 0..255
    int s  = threadIdx.x & 63;    // warp lanes span s => coalesced Pt writes
    int eg = threadIdx.x >> 6;    // 0..3

    float cs[O_DIM];
#pragma unroll
    for (int o = 0; o < O_DIM; o++) cs[o] = C[s * O_DIM + o];
    float bv = Bv[s];

    for (int e = eg * 64; e < eg * 64 + 64; e++) {
        float acc = 0.0f;
#pragma unroll
        for (int o = 0; o < O_DIM; o++) {
            float w = (o < K_HALF) ? __ldg(&Mp[((size_t)o * D_DIM + d) * D_DIM + e])
                                   : __ldg(&Mm[((size_t)(o - K_HALF) * D_DIM + d) * D_DIM + e]);
            acc = fmaf(cs[o], w, acc);
        }
        g_Pt[(size_t)e * K_TOT + d * S_DIM + s] = to_tf32(bv * acc);
    }

    if (s < KX) {
        int j = s;
        float mj[O_DIM];
#pragma unroll
        for (int o = 0; o < O_DIM; o++) mj[o] = M[o * KX + j];   // M is (48, 8, 1)
        for (int e = eg * 64; e < eg * 64 + 64; e++) {
            float acc = 0.0f;
#pragma unroll
            for (int o = 0; o < O_DIM; o++) {
                float w = (o < K_HALF) ? __ldg(&Mp[((size_t)o * D_DIM + d) * D_DIM + e])
                                       : __ldg(&Mm[((size_t)(o - K_HALF) * D_DIM + d) * D_DIM + e]);
                acc = fmaf(mj[o], w, acc);
            }
            g_Pt[(size_t)e * K_TOT + K_G + j * D_DIM + d] = to_tf32(acc);
        }
    }
}

// ---------------- kernel: LDS scan -> g_Aext[m][d*64+s] ----------------
__global__ void k_scan(const float* __restrict__ x, const float* __restrict__ A) {
    int s    = threadIdx.x & 63;
    int half = threadIdx.x >> 6;
    int bd   = blockIdx.x * 2 + half;   // 0..1023
    int b    = bd >> 8;
    int d    = bd & 255;

    float a = A[s];
    float h = 0.0f;
    const float* xp = x + (size_t)b * L_DIM * D_DIM + d;
    float* op = g_Aext + (size_t)b * L_DIM * K_TOT + d * S_DIM + s;

#pragma unroll 1
    for (int l = 0; l < L_DIM; l += 4) {
        float x0 = __ldg(xp + (size_t)l * D_DIM);
        float x1 = __ldg(xp + (size_t)(l + 1) * D_DIM);
        float x2 = __ldg(xp + (size_t)(l + 2) * D_DIM);
        float x3 = __ldg(xp + (size_t)(l + 3) * D_DIM);
        h = fmaf(h, a, x0); op[(size_t)l * K_TOT]       = to_tf32(h);
        h = fmaf(h, a, x1); op[(size_t)(l + 1) * K_TOT] = to_tf32(h);
        h = fmaf(h, a, x2); op[(size_t)(l + 2) * K_TOT] = to_tf32(h);
        h = fmaf(h, a, x3); op[(size_t)(l + 3) * K_TOT] = to_tf32(h);
    }
}

// ---------------- kernel: shift taps (float4) ----------------
__global__ void k_shift(const float* __restrict__ x) {
    int idx = blockIdx.x * 256 + threadIdx.x;   // 4096*8*64 = 2,097,152
    int m  = idx >> 9;
    int r  = idx & 511;
    int j  = r >> 6;
    int d4 = r & 63;
    int b  = m >> 10;
    int l  = m & 1023;
    float4 v = make_float4(0.f, 0.f, 0.f, 0.f);
    if (l >= j)
        v = *(const float4*)(x + ((size_t)b * L_DIM + (l - j)) * D_DIM + d4 * 4);
    v.x = to_tf32(v.x); v.y = to_tf32(v.y); v.z = to_tf32(v.z); v.w = to_tf32(v.w);
    *(float4*)(g_Aext + (size_t)m * K_TOT + K_G + j * D_DIM + d4 * 4) = v;
}

// ---------------- GEMM  part[y][m][e] = sum_k A[m][k] * Pt[e][k] ----------------
// CTA tile 128(M) x 256(N); 16 warps as 2(M) x 8(N); warp tile 64x32.
// 4-stage cp.async pipeline (prefetch depth 3), KTILE=32, single-buffered
// register fragments via ldmatrix.x4. Epilogue: float2 stores to g_part.
#define NST   4
#define KTILE 32
#define KCH   (K_TOT / KSPLIT)          // 4608
#define NSTG  (KCH / KTILE)             // 144
#define A_STG 16384                     // 128 rows * 128B
#define B_STG 32768                     // 256 rows * 128B
#define STG   (A_STG + B_STG)           // 49152
#define SMEM_DYN (NST * STG)            // 196608

__global__ void __launch_bounds__(512, 1)
k_gemm() {
    extern __shared__ char smem[];
    uint32_t sb = smem_u32(smem);

    int tid  = threadIdx.x;
    int lane = tid & 31;
    int wid  = tid >> 5;                 // 0..15
    int wm   = wid >> 3;                 // 0..1
    int wn   = wid & 7;                  // 0..7
    int m0   = blockIdx.x * 128;
    int k0   = blockIdx.y * KCH;

    const float* Ab = g_Aext + (size_t)m0 * K_TOT + k0;
    const float* Bb = g_Pt + k0;

    auto copy_stage = [&](int st) {
        uint32_t base = sb + (st & (NST - 1)) * STG;
        int kf = st * KTILE;
#pragma unroll
        for (int it = 0; it < 6; it++) {
            int id = tid + it * 512;                 // 0..3071 16B chunks
            if (id < 1024) {                         // A: 128 rows x 8 chunks
                int r = id >> 3, ch = id & 7;
                cp_async16(base + r * 128 + ((ch ^ (r & 7)) << 4),
                           Ab + (size_t)r * K_TOT + kf + ch * 4);
            } else {                                 // B: 256 rows x 8 chunks
                int id2 = id - 1024;
                int r = id2 >> 3, ch = id2 & 7;
                cp_async16(base + A_STG + r * 128 + ((ch ^ (r & 7)) << 4),
                           Bb + (size_t)r * K_TOT + kf + ch * 4);
            }
        }
    };

    float acc[4][4][4];
#pragma unroll
    for (int i = 0; i < 4; i++)
#pragma unroll
        for (int j = 0; j < 4; j++)
#pragma unroll
            for (int c = 0; c < 4; c++) acc[i][j][c] = 0.0f;

    copy_stage(0); cp_commit();
    copy_stage(1); cp_commit();
    copy_stage(2); cp_commit();

    // ldmatrix per-lane address components (validated rounds 2-5):
    int sw   = lane & 7;
    int aRow = (lane & 7) + (((lane >> 3) & 1) << 3);
    int aCb  = lane >> 4;
    int bRow = (lane & 7) + ((lane >> 4) << 3);
    int bCb  = (lane >> 3) & 1;

    int lr = lane >> 2;
    int lc = lane & 3;

    for (int ks = 0; ks < NSTG; ks++) {
        asm volatile("cp.async.wait_group 2;" ::: "memory");
        __syncthreads();
        if (ks + 3 < NSTG) copy_stage(ks + 3);       // buffer (ks-1)%4, freed by barrier
        cp_commit();

        uint32_t aBase = sb + (ks & (NST - 1)) * STG;
        uint32_t bBase = aBase + A_STG;
        uint32_t aLane = aBase + (wm * 64 + aRow) * 128;
        uint32_t bLane = bBase + (wn * 32 + bRow) * 128;

#pragma unroll
        for (int kk = 0; kk < 4; kk++) {             // 4 x k8 steps
            uint32_t bF[8];                          // 2 ldsm4: nf pairs {0,1},{2,3}
#pragma unroll
            for (int nfp = 0; nfp < 2; nfp++)
                ldsm4(&bF[nfp * 4],
                      bLane + nfp * 16 * 128 + (((2 * kk + bCb) ^ sw) << 4));
            uint32_t aF[16];
#pragma unroll
            for (int mf = 0; mf < 4; mf++)
                ldsm4(&aF[mf * 4],
                      aLane + mf * 16 * 128 + (((2 * kk + aCb) ^ sw) << 4));
#pragma unroll
            for (int mf = 0; mf < 4; mf++)
#pragma unroll
                for (int nf = 0; nf < 4; nf++)
                    mma8(acc[mf][nf], &aF[mf * 4],
                         &bF[(nf >> 1) * 4 + (nf & 1) * 2]);
        }
    }

    // epilogue: plain stores to this split's partial buffer
    float* po = g_part[blockIdx.y];
#pragma unroll
    for (int mf = 0; mf < 4; mf++) {
#pragma unroll
        for (int nf = 0; nf < 4; nf++) {
            int r = m0 + wm * 64 + mf * 16 + lr;
            int c = wn * 32 + nf * 8 + (lc << 1);
            *(float2*)&po[(size_t)r * E_DIM + c] =
                make_float2(acc[mf][nf][0], acc[mf][nf][1]);
            *(float2*)&po[(size_t)(r + 8) * E_DIM + c] =
                make_float2(acc[mf][nf][2], acc[mf][nf][3]);
        }
    }
}

// ---------------- reduce: out = sum of KSPLIT partials ----------------
__global__ void k_reduce(float* __restrict__ out, int n4) {
    int i = blockIdx.x * 256 + threadIdx.x;
    if (i >= n4) return;
    float4 a = ((const float4*)g_part[0])[i];
    float4 b = ((const float4*)g_part[1])[i];
    float4 c = ((const float4*)g_part[2])[i];
    float4 d = ((const float4*)g_part[3])[i];
    float4 r;
    r.x = (a.x + b.x) + (c.x + d.x);
    r.y = (a.y + b.y) + (c.y + d.y);
    r.z = (a.z + b.z) + (c.z + d.z);
    r.w = (a.w + b.w) + (c.w + d.w);
    ((float4*)out)[i] = r;
}

// ---------------- launch ----------------
extern "C" void kernel_launch(void* const* d_in, const int* in_sizes, int n_in,
                              void* d_out, int out_size) {
    const float* x  = (const float*)d_in[0];
    const float* A  = (const float*)d_in[1];
    const float* Bv = (const float*)d_in[2];
    const float* C  = (const float*)d_in[3];
    const float* M  = (const float*)d_in[4];
    const float* Mp = (const float*)d_in[5];
    const float* Mm = (const float*)d_in[6];
    float* out = (float*)d_out;

    static bool attr_set = false;
    if (!attr_set) {
        cudaFuncSetAttribute(k_gemm, cudaFuncAttributeMaxDynamicSharedMemorySize, SMEM_DYN);
        attr_set = true;
    }

    // k_gemm is launch #4 — the slot ncu has captured in every prior round.
    k_prep<<<D_DIM, 256>>>(C, Bv, M, Mp, Mm);
    k_scan<<<512, 128>>>(x, A);
    k_shift<<<(M_ROWS * KX * 64) / 256, 256>>>(x);

    dim3 grid(M_ROWS / 128, KSPLIT);
    k_gemm<<<grid, 512, SMEM_DYN>>>();

    int n4 = M_ROWS * E_DIM / 4;
    k_reduce<<<(n4 + 255) / 256, 256>>>(out, n4);
}

// round 7
// speedup vs baseline: 1.6845x; 1.3577x over previous
#include <cuda_runtime.h>
#include <cstdint>

// ---------------- problem dims ----------------
#define K_HALF 24
#define S_DIM  64
#define D_DIM  256
#define L_DIM  1024
#define B_SZ   4
#define KX     8
#define O_DIM  48                      // 2*K_HALF
#define K_G    16384                   // D_DIM * S_DIM  (k = d*64 + s)
#define K_TOT  18432                   // K_G + KX*D_DIM (k = 16384 + j*256 + d)
#define M_ROWS 4096                    // B_SZ * L_DIM
#define E_DIM  256
#define KSPLIT 4

// ---------------- scratch (device globals; no cudaMalloc allowed) ----------------
__device__ float g_Pt[(size_t)E_DIM * K_TOT];                  // 19 MB: [e][k] (B, K-major, tf32)
__device__ float g_ck[(size_t)(M_ROWS / 16) * K_G];            // 16 MB: scan state entering each 16-row block
__device__ float g_part[KSPLIT][(size_t)M_ROWS * E_DIM];       // 16 MB: split-K partials

// ---------------- helpers ----------------
__device__ __forceinline__ uint32_t smem_u32(const void* p) {
    uint32_t a;
    asm("{ .reg .u64 t; cvta.to.shared.u64 t, %1; cvt.u32.u64 %0, t; }" : "=r"(a) : "l"(p));
    return a;
}

__device__ __forceinline__ float to_tf32(float v) {
    uint32_t u;
    asm("cvt.rna.tf32.f32 %0, %1;" : "=r"(u) : "f"(v));
    return __uint_as_float(u);
}

__device__ __forceinline__ void cp_async16(uint32_t dst, const void* src) {
    asm volatile("cp.async.cg.shared.global [%0], [%1], 16;" :: "r"(dst), "l"(src));
}
__device__ __forceinline__ void cp_commit() {
    asm volatile("cp.async.commit_group;" ::: "memory");
}

// m16n8k8 tf32 mma, D += A*B (fp32 accum in place)
__device__ __forceinline__ void mma8(float* d, const uint32_t* a, const uint32_t* b) {
    asm volatile(
        "mma.sync.aligned.m16n8k8.row.col.f32.tf32.tf32.f32 "
        "{%0,%1,%2,%3},{%4,%5,%6,%7},{%8,%9},{%0,%1,%2,%3};"
        : "+f"(d[0]), "+f"(d[1]), "+f"(d[2]), "+f"(d[3])
        : "r"(a[0]), "r"(a[1]), "r"(a[2]), "r"(a[3]), "r"(b[0]), "r"(b[1]));
}

__device__ __forceinline__ void ldsm4(uint32_t* r, uint32_t addr) {
    asm volatile("ldmatrix.sync.aligned.m8n8.x4.shared.b16 {%0,%1,%2,%3}, [%4];"
        : "=r"(r[0]), "=r"(r[1]), "=r"(r[2]), "=r"(r[3]) : "r"(addr));
}

__device__ __forceinline__ void sts32(uint32_t addr, float v) {
    asm volatile("st.shared.b32 [%0], %1;" :: "r"(addr), "f"(v));
}

// ---------------- kernel: precompute Pt[e][k] (tf32-rounded), half-d per call ----
__global__ void k_prep(const float* __restrict__ C, const float* __restrict__ Bv,
                       const float* __restrict__ M, const float* __restrict__ Mp,
                       const float* __restrict__ Mm, int d0) {
    __shared__ float Wsh[O_DIM * E_DIM];   // 48 KB
    int d   = blockIdx.x + d0;
    int tid = threadIdx.x;
    int s   = tid & 63;
    int eg  = tid >> 6;

    // cooperative, coalesced load of W_d = W[:, d, :] into smem
    for (int i = tid; i < O_DIM * E_DIM; i += 256) {
        int o = i >> 8, e = i & 255;
        Wsh[i] = (o < K_HALF) ? Mp[((size_t)o * D_DIM + d) * D_DIM + e]
                              : Mm[((size_t)(o - K_HALF) * D_DIM + d) * D_DIM + e];
    }
    __syncthreads();

    float cs[O_DIM];
#pragma unroll
    for (int o = 0; o < O_DIM; o++) cs[o] = C[s * O_DIM + o];
    float bv = Bv[s];

    for (int e = eg * 64; e < eg * 64 + 64; e++) {
        float acc = 0.0f;
#pragma unroll
        for (int o = 0; o < O_DIM; o++)
            acc = fmaf(cs[o], Wsh[o * E_DIM + e], acc);
        g_Pt[(size_t)e * K_TOT + d * S_DIM + s] = to_tf32(bv * acc);
    }

    if (s < KX) {
        int j = s;
        float mj[O_DIM];
#pragma unroll
        for (int o = 0; o < O_DIM; o++) mj[o] = M[o * KX + j];   // M is (48, 8, 1)
        for (int e = eg * 64; e < eg * 64 + 64; e++) {
            float acc = 0.0f;
#pragma unroll
            for (int o = 0; o < O_DIM; o++)
                acc = fmaf(mj[o], Wsh[o * E_DIM + e], acc);
            g_Pt[(size_t)e * K_TOT + K_G + j * D_DIM + d] = to_tf32(acc);
        }
    }
}

// ---------------- kernel: scan checkpoints every 16 rows ----------------
// thread = (b, d, s); stores h entering row-block lb (fp32, full precision).
__global__ void k_ckpt(const float* __restrict__ x, const float* __restrict__ A) {
    int s    = threadIdx.x & 63;
    int half = threadIdx.x >> 6;
    int bd   = blockIdx.x * 2 + half;   // 0..1023
    int b    = bd >> 8;
    int d    = bd & 255;

    float a = A[s];
    float h = 0.0f;
    const float* xp = x + (size_t)b * L_DIM * D_DIM + d;
    float* cp = g_ck + (size_t)(b * (L_DIM / 16)) * K_G + d * S_DIM + s;

#pragma unroll 1
    for (int lb = 0; lb < L_DIM / 16; lb++) {
        cp[(size_t)lb * K_G] = h;       // state entering row lb*16
#pragma unroll
        for (int i = 0; i < 16; i++)
            h = fmaf(h, a, xp[(size_t)(lb * 16 + i) * D_DIM]);
    }
}

// ---------------- fused GEMM  part[ki][m][e] = sum_{k in chunk} A[m][k]*Pt[e][k] --
// A generated in-kernel per 64-col stage: scan from 16-row checkpoints (k < K_G)
// or shifted-x (k >= K_G). B staged via cp.async (Pt is L2-resident).
// CTA 128(M) x 256(N), 16 warps 2x8, warp tile 64x32. Stage = 2 subtiles of 32 cols.
#define KT    64
#define KCH   (K_TOT / KSPLIT)          // 4608
#define NSTG  (KCH / KT)                // 72
#define A_SUB 16384                     // 128 rows * 128B
#define A_STG (2 * A_SUB)               // 32768
#define B_SUB 32768                     // 256 rows * 128B
#define B_STG (2 * B_SUB)               // 65536
#define SMEM_DYN (2 * A_STG + 2 * B_STG)  // 196608

__global__ void __launch_bounds__(512, 1)
k_gemm(const float* __restrict__ x, const float* __restrict__ A) {
    extern __shared__ char smem[];
    uint32_t sb  = smem_u32(smem);
    uint32_t sbB = sb + 2 * A_STG;

    int tid  = threadIdx.x;
    int lane = tid & 31;
    int wid  = tid >> 5;                 // 0..15
    int wm   = wid >> 3;                 // 0..1
    int wn   = wid & 7;                  // 0..7
    int mi   = blockIdx.x;               // 0..31
    int ki   = blockIdx.y;               // 0..3
    int m0   = mi * 128;
    int k0   = ki * KCH;

    // producer thread coords: pc = column in stage (0..63), plb = 16-row block (0..7)
    int pc   = tid & 63;
    int plb  = tid >> 6;
    float a_reg = A[pc];                                   // scan coeff (pc == s)
    size_t ckrow = (size_t)(mi * 8 + plb) * K_G;           // checkpoint row base
    int pcc  = pc & 31;
    uint32_t aColBase = sb /*+ stage*/ ;                   // computed per call

    // ---- produce A stage st into buffer p ----
    auto produce = [&](int st, int p) {
        int k = k0 + st * KT;
        uint32_t abase = sb + p * A_STG + (pc >> 5) * A_SUB;
        if (k < K_G) {
            int d = k >> 6;
            float h = g_ck[ckrow + d * S_DIM + pc];
            const float* xp = x + (size_t)(m0 + plb * 16) * D_DIM + d;
#pragma unroll
            for (int i = 0; i < 16; i++) {
                h = fmaf(h, a_reg, xp[(size_t)i * D_DIM]);
                int r = plb * 16 + i;
                sts32(abase + r * 128 + (((pcc >> 2) ^ (r & 7)) << 4) + ((pcc & 3) << 2),
                      to_tf32(h));
            }
        } else {
            int off = k - K_G;
            int j   = off >> 8;
            int dd  = (off & 255) + pc;
            const float* xp = x + (size_t)(m0 + plb * 16 - j) * D_DIM + dd;
#pragma unroll
            for (int i = 0; i < 16; i++) {
                int gl = (m0 + plb * 16 + i) & (L_DIM - 1);   // local l within sequence
                float v = (gl >= j) ? xp[(size_t)i * D_DIM] : 0.0f;
                int r = plb * 16 + i;
                sts32(abase + r * 128 + (((pcc >> 2) ^ (r & 7)) << 4) + ((pcc & 3) << 2),
                      to_tf32(v));
            }
        }
    };

    // ---- cp.async B stage st into buffer p ----
    auto cpB = [&](int st, int p) {
        uint32_t base = sbB + p * B_STG;
        int kf = k0 + st * KT;
#pragma unroll
        for (int q = 0; q < 8; q++) {
            int id = tid + q * 512;                 // 0..4095 16B chunks
            int t  = id >> 11;                      // subtile
            int r  = (id >> 3) & 255;               // e row
            int ch = id & 7;
            cp_async16(base + t * B_SUB + r * 128 + ((ch ^ (r & 7)) << 4),
                       g_Pt + (size_t)r * K_TOT + kf + t * 32 + ch * 4);
        }
    };

    float acc[4][4][4];
#pragma unroll
    for (int i = 0; i < 4; i++)
#pragma unroll
        for (int j = 0; j < 4; j++)
#pragma unroll
            for (int c = 0; c < 4; c++) acc[i][j][c] = 0.0f;

    // ldmatrix per-lane address components (validated rounds 2-6):
    int sw   = lane & 7;
    int aRow = (lane & 7) + (((lane >> 3) & 1) << 3);
    int aCb  = lane >> 4;
    int bRow = (lane & 7) + ((lane >> 4) << 3);
    int bCb  = (lane >> 3) & 1;

    int lr = lane >> 2;
    int lc = lane & 3;

    // prologue
    produce(0, 0);
    cpB(0, 0); cp_commit();

    for (int ks = 0; ks < NSTG; ks++) {
        asm volatile("cp.async.wait_group 0;" ::: "memory");   // B(ks) complete
        __syncthreads();                                       // A(ks) visible; bufs free
        if (ks + 1 < NSTG) {
            cpB(ks + 1, (ks + 1) & 1); cp_commit();            // lands during mma(ks)
            produce(ks + 1, (ks + 1) & 1);
        }

        uint32_t aT = sb  + (ks & 1) * A_STG;
        uint32_t bT = sbB + (ks & 1) * B_STG;
#pragma unroll
        for (int half = 0; half < 2; half++) {
            uint32_t aLane = aT + half * A_SUB + (wm * 64 + aRow) * 128;
            uint32_t bLane = bT + half * B_SUB + (wn * 32 + bRow) * 128;
#pragma unroll
            for (int kk = 0; kk < 4; kk++) {
                uint32_t bF[8];
#pragma unroll
                for (int nfp = 0; nfp < 2; nfp++)
                    ldsm4(&bF[nfp * 4],
                          bLane + nfp * 16 * 128 + (((2 * kk + bCb) ^ sw) << 4));
                uint32_t aF[16];
#pragma unroll
                for (int mf = 0; mf < 4; mf++)
                    ldsm4(&aF[mf * 4],
                          aLane + mf * 16 * 128 + (((2 * kk + aCb) ^ sw) << 4));
#pragma unroll
                for (int mf = 0; mf < 4; mf++)
#pragma unroll
                    for (int nf = 0; nf < 4; nf++)
                        mma8(acc[mf][nf], &aF[mf * 4],
                             &bF[(nf >> 1) * 4 + (nf & 1) * 2]);
            }
        }
    }

    // epilogue: plain stores to this split's partial buffer
    float* po = g_part[ki];
#pragma unroll
    for (int mf = 0; mf < 4; mf++) {
#pragma unroll
        for (int nf = 0; nf < 4; nf++) {
            int r = m0 + wm * 64 + mf * 16 + lr;
            int c = wn * 32 + nf * 8 + (lc << 1);
            *(float2*)&po[(size_t)r * E_DIM + c] =
                make_float2(acc[mf][nf][0], acc[mf][nf][1]);
            *(float2*)&po[(size_t)(r + 8) * E_DIM + c] =
                make_float2(acc[mf][nf][2], acc[mf][nf][3]);
        }
    }
}

// ---------------- reduce: out = sum of KSPLIT partials ----------------
__global__ void k_reduce(float* __restrict__ out, int n4) {
    int i = blockIdx.x * 256 + threadIdx.x;
    if (i >= n4) return;
    float4 a = ((const float4*)g_part[0])[i];
    float4 b = ((const float4*)g_part[1])[i];
    float4 c = ((const float4*)g_part[2])[i];
    float4 d = ((const float4*)g_part[3])[i];
    float4 r;
    r.x = (a.x + b.x) + (c.x + d.x);
    r.y = (a.y + b.y) + (c.y + d.y);
    r.z = (a.z + b.z) + (c.z + d.z);
    r.w = (a.w + b.w) + (c.w + d.w);
    ((float4*)out)[i] = r;
}

// ---------------- launch ----------------
extern "C" void kernel_launch(void* const* d_in, const int* in_sizes, int n_in,
                              void* d_out, int out_size) {
    const float* x  = (const float*)d_in[0];
    const float* A  = (const float*)d_in[1];
    const float* Bv = (const float*)d_in[2];
    const float* C  = (const float*)d_in[3];
    const float* M  = (const float*)d_in[4];
    const float* Mp = (const float*)d_in[5];
    const float* Mm = (const float*)d_in[6];
    float* out = (float*)d_out;

    static bool attr_set = false;
    if (!attr_set) {
        cudaFuncSetAttribute(k_gemm, cudaFuncAttributeMaxDynamicSharedMemorySize, SMEM_DYN);
        attr_set = true;
    }

    // k_gemm at launch #4 (the slot ncu captures).
    k_prep<<<128, 256>>>(C, Bv, M, Mp, Mm, 0);
    k_prep<<<128, 256>>>(C, Bv, M, Mp, Mm, 128);
    k_ckpt<<<512, 128>>>(x, A);

    dim3 grid(M_ROWS / 128, KSPLIT);
    k_gemm<<<grid, 512, SMEM_DYN>>>(x, A);

    int n4 = M_ROWS * E_DIM / 4;
    k_reduce<<<(n4 + 255) / 256, 256>>>(out, n4);
}

// round 8
// speedup vs baseline: 1.7225x; 1.0226x over previous
#include <cuda_runtime.h>
#include <cstdint>

// ---------------- problem dims ----------------
#define K_HALF 24
#define S_DIM  64
#define D_DIM  256
#define L_DIM  1024
#define B_SZ   4
#define KX     8
#define O_DIM  48                      // 2*K_HALF
#define K_G    16384                   // D_DIM * S_DIM  (k = d*64 + s)
#define K_TOT  18432                   // K_G + KX*D_DIM (k = 16384 + j*256 + d)
#define M_ROWS 4096                    // B_SZ * L_DIM
#define E_DIM  256
#define KSPLIT 4

// ---------------- scratch (device globals; no cudaMalloc allowed) ----------------
__device__ float g_Pt[(size_t)E_DIM * K_TOT];                  // 19 MB: [e][k] (B, K-major, tf32)
__device__ float g_ck[(size_t)(M_ROWS / 16) * K_G];            // 16 MB: scan state entering each 16-row block
__device__ float g_part[KSPLIT][(size_t)M_ROWS * E_DIM];       // 16 MB: split-K partials

// ---------------- helpers ----------------
__device__ __forceinline__ uint32_t smem_u32(const void* p) {
    uint32_t a;
    asm("{ .reg .u64 t; cvta.to.shared.u64 t, %1; cvt.u32.u64 %0, t; }" : "=r"(a) : "l"(p));
    return a;
}

__device__ __forceinline__ float to_tf32(float v) {
    uint32_t u;
    asm("cvt.rna.tf32.f32 %0, %1;" : "=r"(u) : "f"(v));
    return __uint_as_float(u);
}

__device__ __forceinline__ void cp_async16(uint32_t dst, const void* src) {
    asm volatile("cp.async.cg.shared.global [%0], [%1], 16;" :: "r"(dst), "l"(src));
}
__device__ __forceinline__ void cp_commit() {
    asm volatile("cp.async.commit_group;" ::: "memory");
}

// m16n8k8 tf32 mma, D += A*B (fp32 accum in place)
__device__ __forceinline__ void mma8(float* d, const uint32_t* a, const uint32_t* b) {
    asm volatile(
        "mma.sync.aligned.m16n8k8.row.col.f32.tf32.tf32.f32 "
        "{%0,%1,%2,%3},{%4,%5,%6,%7},{%8,%9},{%0,%1,%2,%3};"
        : "+f"(d[0]), "+f"(d[1]), "+f"(d[2]), "+f"(d[3])
        : "r"(a[0]), "r"(a[1]), "r"(a[2]), "r"(a[3]), "r"(b[0]), "r"(b[1]));
}

__device__ __forceinline__ void ldsm4(uint32_t* r, uint32_t addr) {
    asm volatile("ldmatrix.sync.aligned.m8n8.x4.shared.b16 {%0,%1,%2,%3}, [%4];"
        : "=r"(r[0]), "=r"(r[1]), "=r"(r[2]), "=r"(r[3]) : "r"(addr));
}

__device__ __forceinline__ void sts32(uint32_t addr, float v) {
    asm volatile("st.shared.b32 [%0], %1;" :: "r"(addr), "f"(v));
}

// ---------------- kernel: precompute Pt[e][k] (tf32-rounded), half-d per call ----
__global__ void k_prep(const float* __restrict__ C, const float* __restrict__ Bv,
                       const float* __restrict__ M, const float* __restrict__ Mp,
                       const float* __restrict__ Mm, int d0) {
    __shared__ float Wsh[O_DIM * E_DIM];   // 48 KB
    int d   = blockIdx.x + d0;
    int tid = threadIdx.x;
    int s   = tid & 63;
    int eg  = tid >> 6;

    for (int i = tid; i < O_DIM * E_DIM; i += 256) {
        int o = i >> 8, e = i & 255;
        Wsh[i] = (o < K_HALF) ? Mp[((size_t)o * D_DIM + d) * D_DIM + e]
                              : Mm[((size_t)(o - K_HALF) * D_DIM + d) * D_DIM + e];
    }
    __syncthreads();

    float cs[O_DIM];
#pragma unroll
    for (int o = 0; o < O_DIM; o++) cs[o] = C[s * O_DIM + o];
    float bv = Bv[s];

    for (int e = eg * 64; e < eg * 64 + 64; e++) {
        float acc = 0.0f;
#pragma unroll
        for (int o = 0; o < O_DIM; o++)
            acc = fmaf(cs[o], Wsh[o * E_DIM + e], acc);
        g_Pt[(size_t)e * K_TOT + d * S_DIM + s] = to_tf32(bv * acc);
    }

    if (s < KX) {
        int j = s;
        float mj[O_DIM];
#pragma unroll
        for (int o = 0; o < O_DIM; o++) mj[o] = M[o * KX + j];   // M is (48, 8, 1)
        for (int e = eg * 64; e < eg * 64 + 64; e++) {
            float acc = 0.0f;
#pragma unroll
            for (int o = 0; o < O_DIM; o++)
                acc = fmaf(mj[o], Wsh[o * E_DIM + e], acc);
            g_Pt[(size_t)e * K_TOT + K_G + j * D_DIM + d] = to_tf32(acc);
        }
    }
}

// ---------------- kernel: scan checkpoints every 16 rows ----------------
__global__ void k_ckpt(const float* __restrict__ x, const float* __restrict__ A) {
    int s    = threadIdx.x & 63;
    int half = threadIdx.x >> 6;
    int bd   = blockIdx.x * 2 + half;   // 0..1023
    int b    = bd >> 8;
    int d    = bd & 255;

    float a = A[s];
    float h = 0.0f;
    const float* xp = x + (size_t)b * L_DIM * D_DIM + d;
    float* cp = g_ck + (size_t)(b * (L_DIM / 16)) * K_G + d * S_DIM + s;

#pragma unroll 1
    for (int lb = 0; lb < L_DIM / 16; lb++) {
        cp[(size_t)lb * K_G] = h;       // state entering row lb*16
#pragma unroll
        for (int i = 0; i < 16; i++)
            h = fmaf(h, a, xp[(size_t)(lb * 16 + i) * D_DIM]);
    }
}

// ---------------- fused GEMM  part[ki][m][e] = sum_{k in chunk} A[m][k]*Pt[e][k] --
// A generated in-kernel per 64-col stage from 16-row checkpoints / shifted-x.
// This round: checkpoint prefetched one stage early (ck_next), and the producer
// chain runs BETWEEN the two mma half-tiles so its latency overlaps mma issue.
#define KT    64
#define KCH   (K_TOT / KSPLIT)          // 4608
#define NSTG  (KCH / KT)                // 72
#define A_SUB 16384                     // 128 rows * 128B
#define A_STG (2 * A_SUB)               // 32768
#define B_SUB 32768                     // 256 rows * 128B
#define B_STG (2 * B_SUB)               // 65536
#define SMEM_DYN (2 * A_STG + 2 * B_STG)  // 196608

__global__ void __launch_bounds__(512, 1)
k_gemm(const float* __restrict__ x, const float* __restrict__ A) {
    extern __shared__ char smem[];
    uint32_t sb  = smem_u32(smem);
    uint32_t sbB = sb + 2 * A_STG;

    int tid  = threadIdx.x;
    int lane = tid & 31;
    int wid  = tid >> 5;                 // 0..15
    int wm   = wid >> 3;                 // 0..1
    int wn   = wid & 7;                  // 0..7
    int mi   = blockIdx.x;               // 0..31
    int ki   = blockIdx.y;               // 0..3
    int m0   = mi * 128;
    int k0   = ki * KCH;

    // producer coords: pc = column in stage (0..63), plb = 16-row block (0..7)
    int pc   = tid & 63;
    int plb  = tid >> 6;
    float a_reg = A[pc];
    size_t ckrow = (size_t)(mi * 8 + plb) * K_G;
    int pcc  = pc & 31;

    // checkpoint load for stage st (0 if out of range / shift stage)
    auto load_ck = [&](int st) -> float {
        int k = k0 + st * KT;
        if (st < NSTG && k < K_G)
            return g_ck[ckrow + (size_t)(k >> 6) * S_DIM + pc];
        return 0.0f;
    };

    // produce A stage st into buffer p; scan stages take the prefetched ck.
    auto produce = [&](int st, int p, float ck) {
        int k = k0 + st * KT;
        uint32_t abase = sb + p * A_STG + (pc >> 5) * A_SUB;
        if (k < K_G) {
            int d = k >> 6;
            float h = ck;
            const float* xp = x + (size_t)(m0 + plb * 16) * D_DIM + d;
#pragma unroll
            for (int i = 0; i < 16; i++) {
                h = fmaf(h, a_reg, xp[(size_t)i * D_DIM]);
                int r = plb * 16 + i;
                sts32(abase + r * 128 + (((pcc >> 2) ^ (r & 7)) << 4) + ((pcc & 3) << 2),
                      to_tf32(h));
            }
        } else {
            int off = k - K_G;
            int j   = off >> 8;
            int dd  = (off & 255) + pc;
            const float* xp = x + (size_t)(m0 + plb * 16 - j) * D_DIM + dd;
#pragma unroll
            for (int i = 0; i < 16; i++) {
                int gl = (m0 + plb * 16 + i) & (L_DIM - 1);
                float v = (gl >= j) ? xp[(size_t)i * D_DIM] : 0.0f;
                int r = plb * 16 + i;
                sts32(abase + r * 128 + (((pcc >> 2) ^ (r & 7)) << 4) + ((pcc & 3) << 2),
                      to_tf32(v));
            }
        }
    };

    auto cpB = [&](int st, int p) {
        uint32_t base = sbB + p * B_STG;
        int kf = k0 + st * KT;
#pragma unroll
        for (int q = 0; q < 8; q++) {
            int id = tid + q * 512;                 // 0..4095 16B chunks
            int t  = id >> 11;
            int r  = (id >> 3) & 255;
            int ch = id & 7;
            cp_async16(base + t * B_SUB + r * 128 + ((ch ^ (r & 7)) << 4),
                       g_Pt + (size_t)r * K_TOT + kf + t * 32 + ch * 4);
        }
    };

    float acc[4][4][4];
#pragma unroll
    for (int i = 0; i < 4; i++)
#pragma unroll
        for (int j = 0; j < 4; j++)
#pragma unroll
            for (int c = 0; c < 4; c++) acc[i][j][c] = 0.0f;

    // ldmatrix per-lane address components (validated rounds 2-7):
    int sw   = lane & 7;
    int aRow = (lane & 7) + (((lane >> 3) & 1) << 3);
    int aCb  = lane >> 4;
    int bRow = (lane & 7) + ((lane >> 4) << 3);
    int bCb  = (lane >> 3) & 1;

    int lr = lane >> 2;
    int lc = lane & 3;

    // prologue: stage 0 produced inline; prefetch ck for stage 1
    produce(0, 0, load_ck(0));
    float ck_next = load_ck(1);
    cpB(0, 0); cp_commit();

    for (int ks = 0; ks < NSTG; ks++) {
        asm volatile("cp.async.wait_group 0;" ::: "memory");   // B(ks) complete
        __syncthreads();                                       // A(ks) visible; bufs free
        if (ks + 1 < NSTG) { cpB(ks + 1, (ks + 1) & 1); cp_commit(); }

        uint32_t aT = sb  + (ks & 1) * A_STG;
        uint32_t bT = sbB + (ks & 1) * B_STG;

        // ---- mma half 0 ----
        {
            uint32_t aLane = aT + (wm * 64 + aRow) * 128;
            uint32_t bLane = bT + (wn * 32 + bRow) * 128;
#pragma unroll
            for (int kk = 0; kk < 4; kk++) {
                uint32_t bF[8];
#pragma unroll
                for (int nfp = 0; nfp < 2; nfp++)
                    ldsm4(&bF[nfp * 4],
                          bLane + nfp * 16 * 128 + (((2 * kk + bCb) ^ sw) << 4));
                uint32_t aF[16];
#pragma unroll
                for (int mf = 0; mf < 4; mf++)
                    ldsm4(&aF[mf * 4],
                          aLane + mf * 16 * 128 + (((2 * kk + aCb) ^ sw) << 4));
#pragma unroll
                for (int mf = 0; mf < 4; mf++)
#pragma unroll
                    for (int nf = 0; nf < 4; nf++)
                        mma8(acc[mf][nf], &aF[mf * 4],
                             &bF[(nf >> 1) * 4 + (nf & 1) * 2]);
            }
        }

        // ---- producer for stage ks+1 (overlapped with mma) ----
        if (ks + 1 < NSTG) produce(ks + 1, (ks + 1) & 1, ck_next);
        ck_next = load_ck(ks + 2);

        // ---- mma half 1 ----
        {
            uint32_t aLane = aT + A_SUB + (wm * 64 + aRow) * 128;
            uint32_t bLane = bT + B_SUB + (wn * 32 + bRow) * 128;
#pragma unroll
            for (int kk = 0; kk < 4; kk++) {
                uint32_t bF[8];
#pragma unroll
                for (int nfp = 0; nfp < 2; nfp++)
                    ldsm4(&bF[nfp * 4],
                          bLane + nfp * 16 * 128 + (((2 * kk + bCb) ^ sw) << 4));
                uint32_t aF[16];
#pragma unroll
                for (int mf = 0; mf < 4; mf++)
                    ldsm4(&aF[mf * 4],
                          aLane + mf * 16 * 128 + (((2 * kk + aCb) ^ sw) << 4));
#pragma unroll
                for (int mf = 0; mf < 4; mf++)
#pragma unroll
                    for (int nf = 0; nf < 4; nf++)
                        mma8(acc[mf][nf], &aF[mf * 4],
                             &bF[(nf >> 1) * 4 + (nf & 1) * 2]);
            }
        }
    }

    // epilogue: plain stores to this split's partial buffer
    float* po = g_part[ki];
#pragma unroll
    for (int mf = 0; mf < 4; mf++) {
#pragma unroll
        for (int nf = 0; nf < 4; nf++) {
            int r = m0 + wm * 64 + mf * 16 + lr;
            int c = wn * 32 + nf * 8 + (lc << 1);
            *(float2*)&po[(size_t)r * E_DIM + c] =
                make_float2(acc[mf][nf][0], acc[mf][nf][1]);
            *(float2*)&po[(size_t)(r + 8) * E_DIM + c] =
                make_float2(acc[mf][nf][2], acc[mf][nf][3]);
        }
    }
}

// ---------------- reduce: out = sum of KSPLIT partials ----------------
__global__ void k_reduce(float* __restrict__ out, int n4) {
    int i = blockIdx.x * 256 + threadIdx.x;
    if (i >= n4) return;
    float4 a = ((const float4*)g_part[0])[i];
    float4 b = ((const float4*)g_part[1])[i];
    float4 c = ((const float4*)g_part[2])[i];
    float4 d = ((const float4*)g_part[3])[i];
    float4 r;
    r.x = (a.x + b.x) + (c.x + d.x);
    r.y = (a.y + b.y) + (c.y + d.y);
    r.z = (a.z + b.z) + (c.z + d.z);
    r.w = (a.w + b.w) + (c.w + d.w);
    ((float4*)out)[i] = r;
}

// ---------------- launch ----------------
extern "C" void kernel_launch(void* const* d_in, const int* in_sizes, int n_in,
                              void* d_out, int out_size) {
    const float* x  = (const float*)d_in[0];
    const float* A  = (const float*)d_in[1];
    const float* Bv = (const float*)d_in[2];
    const float* C  = (const float*)d_in[3];
    const float* M  = (const float*)d_in[4];
    const float* Mp = (const float*)d_in[5];
    const float* Mm = (const float*)d_in[6];
    float* out = (float*)d_out;

    static bool attr_set = false;
    if (!attr_set) {
        cudaFuncSetAttribute(k_gemm, cudaFuncAttributeMaxDynamicSharedMemorySize, SMEM_DYN);
        attr_set = true;
    }

    // k_gemm at launch #4 (the slot ncu captures).
    k_prep<<<128, 256>>>(C, Bv, M, Mp, Mm, 0);
    k_prep<<<128, 256>>>(C, Bv, M, Mp, Mm, 128);
    k_ckpt<<<512, 128>>>(x, A);

    dim3 grid(M_ROWS / 128, KSPLIT);
    k_gemm<<<grid, 512, SMEM_DYN>>>(x, A);

    int n4 = M_ROWS * E_DIM / 4;
    k_reduce<<<(n4 + 255) / 256, 256>>>(out, n4);
}